// round 11
// baseline (speedup 1.0000x reference)
#include <cuda_runtime.h>
#include <cuda_fp16.h>
#include <cstdint>
#include <math.h>

#define HEAD 64
#define NEMB 1024
#define BATCH 8
#define SEQ   2048
#define MTOT  (BATCH*SEQ)   // 16384
#define NTB   (SEQ/64)      // 32 t-blocks per batch

// scratch: projected k,q,v fp16 (6.3 MB) + fp16 weights + O partials (8 MB)
__device__ __half g_kqv[3][MTOT][HEAD];
__device__ __half g_Wh[3][HEAD][NEMB];   // Wh[p][n][k] = half(W[p][k][n])
__device__ float  g_opart[2][MTOT][HEAD];

// D += A*B : m16n8k16 fp16 inputs, fp32 accum
__device__ __forceinline__ void mma16(float c[4], const uint32_t a[4], uint32_t b0, uint32_t b1) {
    asm volatile(
        "mma.sync.aligned.m16n8k16.row.col.f32.f16.f16.f32 "
        "{%0,%1,%2,%3}, {%4,%5,%6,%7}, {%8,%9}, {%0,%1,%2,%3};"
        : "+f"(c[0]), "+f"(c[1]), "+f"(c[2]), "+f"(c[3])
        : "r"(a[0]), "r"(a[1]), "r"(a[2]), "r"(a[3]), "r"(b0), "r"(b1));
}

__device__ __forceinline__ uint32_t f2h2(float a, float b) {
    __half2 h = __floats2half2_rn(a, b);
    return *(uint32_t*)&h;
}

// ---------------------------------------------------------------------------
// W transpose + fp16 round:  g_Wh[p][n][k] = half(W[p][k][n])
// ---------------------------------------------------------------------------
__global__ __launch_bounds__(256) void wt_kernel(
    const float* __restrict__ Wk, const float* __restrict__ Wq, const float* __restrict__ Wv)
{
    __shared__ float t[64][17];
    const float* __restrict__ W = (blockIdx.y == 0) ? Wk : ((blockIdx.y == 1) ? Wq : Wv);
    const int k0 = blockIdx.x * 16;
    const int tid = threadIdx.x;
    #pragma unroll
    for (int i = 0; i < 4; ++i) {
        int idx = i * 256 + tid;
        int kk = idx >> 6, n = idx & 63;
        t[n][kk] = W[(size_t)(k0 + kk) * HEAD + n];
    }
    __syncthreads();
    #pragma unroll
    for (int i = 0; i < 4; ++i) {
        int idx = i * 256 + tid;
        int n = idx >> 4, kk = idx & 15;
        g_Wh[blockIdx.y][n][k0 + kk] = __float2half_rn(t[n][kk]);
    }
}

// ---------------------------------------------------------------------------
// Projection via fp16 mma m16n8k16 (unchanged from R9).
// CTA: 128(m) x 192(n), K chunk 32, ping-pong buffers, 1 barrier/chunk.
// ---------------------------------------------------------------------------
#define PST 40
#define PROJ_X_H   (128 * PST)
#define PROJ_W_H   (192 * PST)
#define PROJ_SMEM  ((2 * PROJ_X_H + 2 * PROJ_W_H) * 2)   // 51200 B

__global__ __launch_bounds__(256, 1) void proj_mma_kernel(
    const float* __restrict__ x,
    const float* __restrict__ bk, const float* __restrict__ bq, const float* __restrict__ bv)
{
    extern __shared__ __half psm[];
    __half* xsb = psm;
    __half* wsb = psm + 2 * PROJ_X_H;

    const int tid  = threadIdx.x;
    const int wid  = tid >> 5, lane = tid & 31;
    const int wm   = wid >> 1, wn = wid & 1;
    const int g    = lane >> 2, t = lane & 3;
    const int m0   = blockIdx.x * 128;

    int xrow[4], xcol[4], wrow[3], wcol[3];
    #pragma unroll
    for (int i = 0; i < 4; ++i) { int idx = i * 256 + tid; xrow[i] = idx >> 3; xcol[i] = (idx & 7) * 4; }
    #pragma unroll
    for (int i = 0; i < 3; ++i) { int idx = i * 256 + tid; wrow[i] = idx >> 2; wcol[i] = (idx & 3) * 8; }

    float c[2][12][4];
    #pragma unroll
    for (int mt = 0; mt < 2; ++mt)
        #pragma unroll
        for (int nt = 0; nt < 12; ++nt)
            #pragma unroll
            for (int r = 0; r < 4; ++r) c[mt][nt][r] = 0.f;

    uint2 xr[4];
    uint4 wr[3];

    #pragma unroll
    for (int i = 0; i < 4; ++i) {
        float4 v = *(const float4*)&x[(size_t)(m0 + xrow[i]) * NEMB + xcol[i]];
        xr[i].x = f2h2(v.x, v.y); xr[i].y = f2h2(v.z, v.w);
    }
    #pragma unroll
    for (int i = 0; i < 3; ++i)
        wr[i] = *(const uint4*)&g_Wh[wrow[i] >> 6][wrow[i] & 63][wcol[i]];
    #pragma unroll
    for (int i = 0; i < 4; ++i)
        *(uint2*)&xsb[xrow[i] * PST + xcol[i]] = xr[i];
    #pragma unroll
    for (int i = 0; i < 3; ++i)
        *(uint4*)&wsb[wrow[i] * PST + wcol[i]] = wr[i];
    __syncthreads();

    for (int ch = 0; ch < 32; ++ch) {
        const int cur = ch & 1;
        __half* xs = xsb + cur * PROJ_X_H;
        __half* ws = wsb + cur * PROJ_W_H;
        __half* xsn = xsb + (cur ^ 1) * PROJ_X_H;
        __half* wsn = wsb + (cur ^ 1) * PROJ_W_H;

        if (ch < 31) {
            const int k1 = (ch + 1) * 32;
            #pragma unroll
            for (int i = 0; i < 4; ++i) {
                float4 v = *(const float4*)&x[(size_t)(m0 + xrow[i]) * NEMB + k1 + xcol[i]];
                xr[i].x = f2h2(v.x, v.y); xr[i].y = f2h2(v.z, v.w);
            }
            #pragma unroll
            for (int i = 0; i < 3; ++i)
                wr[i] = *(const uint4*)&g_Wh[wrow[i] >> 6][wrow[i] & 63][k1 + wcol[i]];
        }

        uint32_t A[2][2][4];
        #pragma unroll
        for (int mt = 0; mt < 2; ++mt) {
            const int row = wm * 32 + mt * 16 + g;
            #pragma unroll
            for (int kt = 0; kt < 2; ++kt) {
                const int col = kt * 16 + 2 * t;
                A[mt][kt][0] = *(const uint32_t*)&xs[(row    ) * PST + col    ];
                A[mt][kt][1] = *(const uint32_t*)&xs[(row + 8) * PST + col    ];
                A[mt][kt][2] = *(const uint32_t*)&xs[(row    ) * PST + col + 8];
                A[mt][kt][3] = *(const uint32_t*)&xs[(row + 8) * PST + col + 8];
            }
        }
        #pragma unroll
        for (int kt = 0; kt < 2; ++kt) {
            #pragma unroll
            for (int nt = 0; nt < 12; ++nt) {
                const int ng = wn * 96 + nt * 8 + g;
                const int col = kt * 16 + 2 * t;
                uint32_t b0 = *(const uint32_t*)&ws[ng * PST + col    ];
                uint32_t b1 = *(const uint32_t*)&ws[ng * PST + col + 8];
                mma16(c[0][nt], A[0][kt], b0, b1);
                mma16(c[1][nt], A[1][kt], b0, b1);
            }
        }

        if (ch < 31) {
            #pragma unroll
            for (int i = 0; i < 4; ++i)
                *(uint2*)&xsn[xrow[i] * PST + xcol[i]] = xr[i];
            #pragma unroll
            for (int i = 0; i < 3; ++i)
                *(uint4*)&wsn[wrow[i] * PST + wcol[i]] = wr[i];
        }
        __syncthreads();
    }

    const float* biases[3] = {bk, bq, bv};
    #pragma unroll
    for (int nt = 0; nt < 12; ++nt) {
        const int ng0 = wn * 96 + nt * 8;
        const int p = ng0 >> 6;
        const int n = (ng0 & 63) + 2 * t;
        const float* __restrict__ bias = biases[p];
        const float b0 = bias[n], b1 = bias[n + 1];
        #pragma unroll
        for (int mt = 0; mt < 2; ++mt) {
            const int row = m0 + wm * 32 + mt * 16 + g;
            *(uint32_t*)&g_kqv[p][row    ][n] = f2h2(c[mt][nt][0] + b0, c[mt][nt][1] + b1);
            *(uint32_t*)&g_kqv[p][row + 8][n] = f2h2(c[mt][nt][2] + b0, c[mt][nt][3] + b1);
        }
    }
}

// ---------------------------------------------------------------------------
// Attention, s-parity split: grid (16, 2, 8) = 256 CTAs, 2 CTAs/SM.
// CTA (i, sy, b) handles t-blocks {i, 31-i}, s-blocks with sb%2==sy
// (17/16 iterations -> balanced). Partial O -> g_opart[sy]; reduce adds.
// ---------------------------------------------------------------------------
#define ASTH 72
#define TILE_H (64 * ASTH)
#define ATTN_SMEM (6 * TILE_H * 2)          // 55296 B -> 2 CTAs/SM

__device__ __forceinline__ float softplus_f(float x) {
    return fmaxf(x, 0.f) + __logf(1.f + __expf(-fabsf(x)));
}

__global__ __launch_bounds__(256, 2) void attn_kernel()
{
    extern __shared__ __half smh[];
    __half* ks  = smh;                       // [64][ASTH]  K tile [t][h]
    __half* qsb = smh + TILE_H;              // 2 x Q tiles [s][h]
    __half* vTb = smh + 3 * TILE_H;          // 2 x V transposed [h][s]
    __half* Ps  = smh + 5 * TILE_H;          // P tile [t][s]

    const int sy   = blockIdx.y;             // s-parity
    const int b    = blockIdx.z;
    const int tid  = threadIdx.x;
    const int wid  = tid >> 5, lane = tid & 31;
    const int wm   = wid >> 1, wn = wid & 1;
    const int g    = lane >> 2, t = lane & 3;
    const int lr   = tid & 63;
    const int lh   = (tid >> 6) * 4;
    const int trow = wm * 16 + g;

    int qrow[4], qcol[4];
    #pragma unroll
    for (int i = 0; i < 4; ++i) { int idx = i * 256 + tid; qrow[i] = idx >> 4; qcol[i] = (idx & 15) * 4; }

    const __half* __restrict__ Kg = &g_kqv[0][(size_t)b * SEQ][0];
    const __half* __restrict__ Qg = &g_kqv[1][(size_t)b * SEQ][0];
    const __half* __restrict__ Vg = &g_kqv[2][(size_t)b * SEQ][0];

    for (int hf = 0; hf < 2; ++hf) {
        const int tb = hf ? (NTB - 1 - (int)blockIdx.x) : (int)blockIdx.x;

        // K tile [t][h]
        #pragma unroll
        for (int i = 0; i < 4; ++i) {
            uint2 u = *(const uint2*)&Kg[(size_t)(tb * 64 + qrow[i]) * HEAD + qcol[i]];
            *(uint2*)&ks[qrow[i] * ASTH + qcol[i]] = u;
        }

        // prologue: first s-block (sb = sy) into buffer 0
        if (sy <= tb) {
            const size_t s0 = (size_t)sy * 64;
            #pragma unroll
            for (int i = 0; i < 4; ++i) {
                uint2 u = *(const uint2*)&Qg[(s0 + qrow[i]) * HEAD + qcol[i]];
                *(uint2*)&qsb[qrow[i] * ASTH + qcol[i]] = u;
            }
            #pragma unroll
            for (int r = 0; r < 4; ++r) {
                int hh = lh + r * 16;
                uint2 u = *(const uint2*)&Vg[(s0 + lr) * HEAD + hh];
                __half2 p0 = *(__half2*)&u.x;
                __half2 p1 = *(__half2*)&u.y;
                vTb[(hh + 0) * ASTH + lr] = __low2half(p0);
                vTb[(hh + 1) * ASTH + lr] = __high2half(p0);
                vTb[(hh + 2) * ASTH + lr] = __low2half(p1);
                vTb[(hh + 3) * ASTH + lr] = __high2half(p1);
            }
        }
        __syncthreads();

        // K A-fragments, resident across the s-loop
        uint32_t A[4][4];
        #pragma unroll
        for (int kt = 0; kt < 4; ++kt) {
            const int col = kt * 16 + 2 * t;
            A[kt][0] = *(const uint32_t*)&ks[(trow    ) * ASTH + col    ];
            A[kt][1] = *(const uint32_t*)&ks[(trow + 8) * ASTH + col    ];
            A[kt][2] = *(const uint32_t*)&ks[(trow    ) * ASTH + col + 8];
            A[kt][3] = *(const uint32_t*)&ks[(trow + 8) * ASTH + col + 8];
        }

        float o[4][4];
        #pragma unroll
        for (int nt = 0; nt < 4; ++nt)
            #pragma unroll
            for (int r = 0; r < 4; ++r) o[nt][r] = 0.f;

        uint2 qrh[4], vrh[4];

        int it = 0;
        for (int sb = sy; sb <= tb; sb += 2, ++it) {
            const int cur = it & 1;
            __half* qs  = qsb + cur * TILE_H;
            __half* vT  = vTb + cur * TILE_H;
            __half* qsn = qsb + (cur ^ 1) * TILE_H;
            __half* vTn = vTb + (cur ^ 1) * TILE_H;

            // prefetch s-block sb+2
            if (sb + 2 <= tb) {
                const size_t s1 = (size_t)(sb + 2) * 64;
                #pragma unroll
                for (int i = 0; i < 4; ++i)
                    qrh[i] = *(const uint2*)&Qg[(s1 + qrow[i]) * HEAD + qcol[i]];
                #pragma unroll
                for (int r = 0; r < 4; ++r)
                    vrh[r] = *(const uint2*)&Vg[(s1 + lr) * HEAD + (lh + r * 16)];
            }

            // S = K . Q^T
            float s_c[4][4];
            #pragma unroll
            for (int nt = 0; nt < 4; ++nt)
                #pragma unroll
                for (int r = 0; r < 4; ++r) s_c[nt][r] = 0.f;
            #pragma unroll
            for (int kt = 0; kt < 4; ++kt) {
                const int col = kt * 16 + 2 * t;
                #pragma unroll
                for (int nt = 0; nt < 4; ++nt) {
                    const int srow = wn * 32 + nt * 8 + g;
                    uint32_t b0 = *(const uint32_t*)&qs[srow * ASTH + col    ];
                    uint32_t b1 = *(const uint32_t*)&qs[srow * ASTH + col + 8];
                    mma16(s_c[nt], A[kt], b0, b1);
                }
            }

            // softplus + causal mask -> Ps
            const bool diag = (sb == tb);
            #pragma unroll
            for (int nt = 0; nt < 4; ++nt) {
                const int sc = wn * 32 + nt * 8 + 2 * t;
                float p0 = softplus_f(s_c[nt][0] * 0.03125f);
                float p1 = softplus_f(s_c[nt][1] * 0.03125f);
                float p2 = softplus_f(s_c[nt][2] * 0.03125f);
                float p3 = softplus_f(s_c[nt][3] * 0.03125f);
                if (diag) {
                    if (sc     > trow    ) p0 = 0.f;
                    if (sc + 1 > trow    ) p1 = 0.f;
                    if (sc     > trow + 8) p2 = 0.f;
                    if (sc + 1 > trow + 8) p3 = 0.f;
                }
                *(uint32_t*)&Ps[(trow    ) * ASTH + sc] = f2h2(p0, p1);
                *(uint32_t*)&Ps[(trow + 8) * ASTH + sc] = f2h2(p2, p3);
            }
            __syncthreads();

            // O += P . V
            #pragma unroll
            for (int kt = 0; kt < 4; ++kt) {
                const int col = kt * 16 + 2 * t;
                uint32_t pa[4];
                pa[0] = *(const uint32_t*)&Ps[(trow    ) * ASTH + col    ];
                pa[1] = *(const uint32_t*)&Ps[(trow + 8) * ASTH + col    ];
                pa[2] = *(const uint32_t*)&Ps[(trow    ) * ASTH + col + 8];
                pa[3] = *(const uint32_t*)&Ps[(trow + 8) * ASTH + col + 8];
                #pragma unroll
                for (int nt = 0; nt < 4; ++nt) {
                    const int hrow = wn * 32 + nt * 8 + g;
                    uint32_t b0 = *(const uint32_t*)&vT[hrow * ASTH + col    ];
                    uint32_t b1 = *(const uint32_t*)&vT[hrow * ASTH + col + 8];
                    mma16(o[nt], pa, b0, b1);
                }
            }

            if (sb + 2 <= tb) {
                #pragma unroll
                for (int i = 0; i < 4; ++i)
                    *(uint2*)&qsn[qrow[i] * ASTH + qcol[i]] = qrh[i];
                #pragma unroll
                for (int r = 0; r < 4; ++r) {
                    int hh = lh + r * 16;
                    __half2 p0 = *(__half2*)&vrh[r].x;
                    __half2 p1 = *(__half2*)&vrh[r].y;
                    vTn[(hh + 0) * ASTH + lr] = __low2half(p0);
                    vTn[(hh + 1) * ASTH + lr] = __high2half(p0);
                    vTn[(hh + 2) * ASTH + lr] = __low2half(p1);
                    vTn[(hh + 3) * ASTH + lr] = __high2half(p1);
                }
            }
            __syncthreads();
        }

        // write O partial tile (fp32)
        {
            float* __restrict__ op = &g_opart[sy][(size_t)b * SEQ + tb * 64 + trow][0];
            #pragma unroll
            for (int nt = 0; nt < 4; ++nt) {
                const int col = wn * 32 + nt * 8 + 2 * t;
                *(float2*)&op[col]             = make_float2(o[nt][0], o[nt][1]);
                *(float2*)&op[8 * HEAD + col]  = make_float2(o[nt][2], o[nt][3]);
            }
        }
        __syncthreads();   // before next hf overwrites ks/buffers
    }
}

// ---------------------------------------------------------------------------
// Reduce: out = g_opart[0] + g_opart[1]
// ---------------------------------------------------------------------------
__global__ __launch_bounds__(256) void reduce_kernel(float* __restrict__ out)
{
    const int i = blockIdx.x * 256 + threadIdx.x;   // float4 index
    const float4 a = ((const float4*)g_opart[0])[i];
    const float4 c = ((const float4*)g_opart[1])[i];
    float4 r;
    r.x = a.x + c.x; r.y = a.y + c.y; r.z = a.z + c.z; r.w = a.w + c.w;
    ((float4*)out)[i] = r;
}

// ---------------------------------------------------------------------------
extern "C" void kernel_launch(void* const* d_in, const int* in_sizes, int n_in,
                              void* d_out, int out_size)
{
    const float* x  = (const float*)d_in[0];
    const float* Wk = (const float*)d_in[1];
    const float* bk = (const float*)d_in[2];
    const float* Wq = (const float*)d_in[3];
    const float* bq = (const float*)d_in[4];
    const float* Wv = (const float*)d_in[5];
    const float* bv = (const float*)d_in[6];
    float* out = (float*)d_out;

    static int init = 0;
    if (!init) {
        cudaFuncSetAttribute(attn_kernel, cudaFuncAttributeMaxDynamicSharedMemorySize, ATTN_SMEM);
        cudaFuncSetAttribute(proj_mma_kernel, cudaFuncAttributeMaxDynamicSharedMemorySize, PROJ_SMEM);
        init = 1;
    }

    dim3 wg(NEMB / 16, 3);
    wt_kernel<<<wg, 256>>>(Wk, Wq, Wv);

    proj_mma_kernel<<<MTOT / 128, 256, PROJ_SMEM>>>(x, bk, bq, bv);

    dim3 ag(NTB / 2, 2, BATCH);
    attn_kernel<<<ag, 256, ATTN_SMEM>>>();

    reduce_kernel<<<(MTOT * HEAD / 4) / 256, 256>>>(out);
}

// round 12
// speedup vs baseline: 1.1333x; 1.1333x over previous
#include <cuda_runtime.h>
#include <cuda_fp16.h>
#include <cstdint>
#include <math.h>

#define HEAD 64
#define NEMB 1024
#define BATCH 8
#define SEQ   2048
#define MTOT  (BATCH*SEQ)   // 16384
#define NTB   (SEQ/64)      // 32 t-blocks per batch

// scratch: projected k,q,v fp16 (6.3 MB) + fp16 weights
__device__ __half g_kqv[3][MTOT][HEAD];
__device__ __half g_Wh[3][HEAD][NEMB];   // Wh[p][n][k] = half(W[p][k][n])

// D += A*B : m16n8k16 fp16 inputs, fp32 accum
__device__ __forceinline__ void mma16(float c[4], const uint32_t a[4], uint32_t b0, uint32_t b1) {
    asm volatile(
        "mma.sync.aligned.m16n8k16.row.col.f32.f16.f16.f32 "
        "{%0,%1,%2,%3}, {%4,%5,%6,%7}, {%8,%9}, {%0,%1,%2,%3};"
        : "+f"(c[0]), "+f"(c[1]), "+f"(c[2]), "+f"(c[3])
        : "r"(a[0]), "r"(a[1]), "r"(a[2]), "r"(a[3]), "r"(b0), "r"(b1));
}

__device__ __forceinline__ uint32_t f2h2(float a, float b) {
    __half2 h = __floats2half2_rn(a, b);
    return *(uint32_t*)&h;
}

// ---------------------------------------------------------------------------
// W transpose + fp16 round:  g_Wh[p][n][k] = half(W[p][k][n])
// ---------------------------------------------------------------------------
__global__ __launch_bounds__(256) void wt_kernel(
    const float* __restrict__ Wk, const float* __restrict__ Wq, const float* __restrict__ Wv)
{
    __shared__ float t[64][17];
    const float* __restrict__ W = (blockIdx.y == 0) ? Wk : ((blockIdx.y == 1) ? Wq : Wv);
    const int k0 = blockIdx.x * 16;
    const int tid = threadIdx.x;
    #pragma unroll
    for (int i = 0; i < 4; ++i) {
        int idx = i * 256 + tid;
        int kk = idx >> 6, n = idx & 63;
        t[n][kk] = W[(size_t)(k0 + kk) * HEAD + n];
    }
    __syncthreads();
    #pragma unroll
    for (int i = 0; i < 4; ++i) {
        int idx = i * 256 + tid;
        int n = idx >> 4, kk = idx & 15;
        g_Wh[blockIdx.y][n][k0 + kk] = __float2half_rn(t[n][kk]);
    }
}

// ---------------------------------------------------------------------------
// Projection via fp16 mma m16n8k16 (unchanged from R9).
// CTA: 128(m) x 192(n), K chunk 32, ping-pong buffers, 1 barrier/chunk.
// ---------------------------------------------------------------------------
#define PST 40
#define PROJ_X_H   (128 * PST)
#define PROJ_W_H   (192 * PST)
#define PROJ_SMEM  ((2 * PROJ_X_H + 2 * PROJ_W_H) * 2)   // 51200 B

__global__ __launch_bounds__(256, 1) void proj_mma_kernel(
    const float* __restrict__ x,
    const float* __restrict__ bk, const float* __restrict__ bq, const float* __restrict__ bv)
{
    extern __shared__ __half psm[];
    __half* xsb = psm;
    __half* wsb = psm + 2 * PROJ_X_H;

    const int tid  = threadIdx.x;
    const int wid  = tid >> 5, lane = tid & 31;
    const int wm   = wid >> 1, wn = wid & 1;
    const int g    = lane >> 2, t = lane & 3;
    const int m0   = blockIdx.x * 128;

    int xrow[4], xcol[4], wrow[3], wcol[3];
    #pragma unroll
    for (int i = 0; i < 4; ++i) { int idx = i * 256 + tid; xrow[i] = idx >> 3; xcol[i] = (idx & 7) * 4; }
    #pragma unroll
    for (int i = 0; i < 3; ++i) { int idx = i * 256 + tid; wrow[i] = idx >> 2; wcol[i] = (idx & 3) * 8; }

    float c[2][12][4];
    #pragma unroll
    for (int mt = 0; mt < 2; ++mt)
        #pragma unroll
        for (int nt = 0; nt < 12; ++nt)
            #pragma unroll
            for (int r = 0; r < 4; ++r) c[mt][nt][r] = 0.f;

    uint2 xr[4];
    uint4 wr[3];

    #pragma unroll
    for (int i = 0; i < 4; ++i) {
        float4 v = *(const float4*)&x[(size_t)(m0 + xrow[i]) * NEMB + xcol[i]];
        xr[i].x = f2h2(v.x, v.y); xr[i].y = f2h2(v.z, v.w);
    }
    #pragma unroll
    for (int i = 0; i < 3; ++i)
        wr[i] = *(const uint4*)&g_Wh[wrow[i] >> 6][wrow[i] & 63][wcol[i]];
    #pragma unroll
    for (int i = 0; i < 4; ++i)
        *(uint2*)&xsb[xrow[i] * PST + xcol[i]] = xr[i];
    #pragma unroll
    for (int i = 0; i < 3; ++i)
        *(uint4*)&wsb[wrow[i] * PST + wcol[i]] = wr[i];
    __syncthreads();

    for (int ch = 0; ch < 32; ++ch) {
        const int cur = ch & 1;
        __half* xs = xsb + cur * PROJ_X_H;
        __half* ws = wsb + cur * PROJ_W_H;
        __half* xsn = xsb + (cur ^ 1) * PROJ_X_H;
        __half* wsn = wsb + (cur ^ 1) * PROJ_W_H;

        if (ch < 31) {
            const int k1 = (ch + 1) * 32;
            #pragma unroll
            for (int i = 0; i < 4; ++i) {
                float4 v = *(const float4*)&x[(size_t)(m0 + xrow[i]) * NEMB + k1 + xcol[i]];
                xr[i].x = f2h2(v.x, v.y); xr[i].y = f2h2(v.z, v.w);
            }
            #pragma unroll
            for (int i = 0; i < 3; ++i)
                wr[i] = *(const uint4*)&g_Wh[wrow[i] >> 6][wrow[i] & 63][k1 + wcol[i]];
        }

        uint32_t A[2][2][4];
        #pragma unroll
        for (int mt = 0; mt < 2; ++mt) {
            const int row = wm * 32 + mt * 16 + g;
            #pragma unroll
            for (int kt = 0; kt < 2; ++kt) {
                const int col = kt * 16 + 2 * t;
                A[mt][kt][0] = *(const uint32_t*)&xs[(row    ) * PST + col    ];
                A[mt][kt][1] = *(const uint32_t*)&xs[(row + 8) * PST + col    ];
                A[mt][kt][2] = *(const uint32_t*)&xs[(row    ) * PST + col + 8];
                A[mt][kt][3] = *(const uint32_t*)&xs[(row + 8) * PST + col + 8];
            }
        }
        #pragma unroll
        for (int kt = 0; kt < 2; ++kt) {
            #pragma unroll
            for (int nt = 0; nt < 12; ++nt) {
                const int ng = wn * 96 + nt * 8 + g;
                const int col = kt * 16 + 2 * t;
                uint32_t b0 = *(const uint32_t*)&ws[ng * PST + col    ];
                uint32_t b1 = *(const uint32_t*)&ws[ng * PST + col + 8];
                mma16(c[0][nt], A[0][kt], b0, b1);
                mma16(c[1][nt], A[1][kt], b0, b1);
            }
        }

        if (ch < 31) {
            #pragma unroll
            for (int i = 0; i < 4; ++i)
                *(uint2*)&xsn[xrow[i] * PST + xcol[i]] = xr[i];
            #pragma unroll
            for (int i = 0; i < 3; ++i)
                *(uint4*)&wsn[wrow[i] * PST + wcol[i]] = wr[i];
        }
        __syncthreads();
    }

    const float* biases[3] = {bk, bq, bv};
    #pragma unroll
    for (int nt = 0; nt < 12; ++nt) {
        const int ng0 = wn * 96 + nt * 8;
        const int p = ng0 >> 6;
        const int n = (ng0 & 63) + 2 * t;
        const float* __restrict__ bias = biases[p];
        const float b0 = bias[n], b1 = bias[n + 1];
        #pragma unroll
        for (int mt = 0; mt < 2; ++mt) {
            const int row = m0 + wm * 32 + mt * 16 + g;
            *(uint32_t*)&g_kqv[p][row    ][n] = f2h2(c[mt][nt][0] + b0, c[mt][nt][1] + b1);
            *(uint32_t*)&g_kqv[p][row + 8][n] = f2h2(c[mt][nt][2] + b0, c[mt][nt][3] + b1);
        }
    }
}

// ---------------------------------------------------------------------------
// Attention, P-in-registers. 256 threads, 64x64 tiles, t-blocks {i, 31-i}
// sequential, grid (16,8), one wave. Warp (wm, wn): S tile = 16 t-rows x
// 32 s-cols (wn half). S accumulator fragments are repacked DIRECTLY into
// O-mma A fragments (no smem round-trip); each warp accumulates partial O
// over its own 32 s-cols x all 64 h. Cross-wn reduction once per t-block.
// One barrier per s-iteration (ping-pong Q/V buffers).
// ---------------------------------------------------------------------------
#define ASTH 72
#define TILE_H (64 * ASTH)
#define ATTN_SMEM (5 * TILE_H * 2)          // ks + 2*qs + 2*vT = 46080 B

__device__ __forceinline__ float softplus_f(float x) {
    return fmaxf(x, 0.f) + __logf(1.f + __expf(-fabsf(x)));
}

__global__ __launch_bounds__(256, 1) void attn_kernel(float* __restrict__ out)
{
    extern __shared__ __half smh[];
    __half* ks  = smh;                       // [64][ASTH]  K tile [t][h]
    __half* qsb = smh + TILE_H;              // 2 x Q tiles [s][h]
    __half* vTb = smh + 3 * TILE_H;          // 2 x V transposed [h][s]
    float*  stage = (float*)qsb;             // epilogue staging (16 KB, reused)

    const int b    = blockIdx.y;
    const int tid  = threadIdx.x;
    const int wid  = tid >> 5, lane = tid & 31;
    const int wm   = wid >> 1, wn = wid & 1;
    const int g    = lane >> 2, t = lane & 3;
    const int lr   = tid & 63;               // V loader row (s)
    const int lh   = (tid >> 6) * 4;         // V loader col base (h)
    const int trow = wm * 16 + g;

    int qrow[4], qcol[4];
    #pragma unroll
    for (int i = 0; i < 4; ++i) { int idx = i * 256 + tid; qrow[i] = idx >> 4; qcol[i] = (idx & 15) * 4; }

    const __half* __restrict__ Kg = &g_kqv[0][(size_t)b * SEQ][0];
    const __half* __restrict__ Qg = &g_kqv[1][(size_t)b * SEQ][0];
    const __half* __restrict__ Vg = &g_kqv[2][(size_t)b * SEQ][0];

    for (int hf = 0; hf < 2; ++hf) {
        const int tb = hf ? (NTB - 1 - (int)blockIdx.x) : (int)blockIdx.x;

        // K tile [t][h]
        #pragma unroll
        for (int i = 0; i < 4; ++i) {
            uint2 u = *(const uint2*)&Kg[(size_t)(tb * 64 + qrow[i]) * HEAD + qcol[i]];
            *(uint2*)&ks[qrow[i] * ASTH + qcol[i]] = u;
        }

        // prologue: sb=0 Q/V into buffer 0
        {
            #pragma unroll
            for (int i = 0; i < 4; ++i) {
                uint2 u = *(const uint2*)&Qg[(size_t)qrow[i] * HEAD + qcol[i]];
                *(uint2*)&qsb[qrow[i] * ASTH + qcol[i]] = u;
            }
            #pragma unroll
            for (int r = 0; r < 4; ++r) {
                int hh = lh + r * 16;
                uint2 u = *(const uint2*)&Vg[(size_t)lr * HEAD + hh];
                __half2 p0 = *(__half2*)&u.x;
                __half2 p1 = *(__half2*)&u.y;
                vTb[(hh + 0) * ASTH + lr] = __low2half(p0);
                vTb[(hh + 1) * ASTH + lr] = __high2half(p0);
                vTb[(hh + 2) * ASTH + lr] = __low2half(p1);
                vTb[(hh + 3) * ASTH + lr] = __high2half(p1);
            }
        }
        __syncthreads();

        // K A-fragments, resident across the s-loop
        uint32_t A[4][4];
        #pragma unroll
        for (int kt = 0; kt < 4; ++kt) {
            const int col = kt * 16 + 2 * t;
            A[kt][0] = *(const uint32_t*)&ks[(trow    ) * ASTH + col    ];
            A[kt][1] = *(const uint32_t*)&ks[(trow + 8) * ASTH + col    ];
            A[kt][2] = *(const uint32_t*)&ks[(trow    ) * ASTH + col + 8];
            A[kt][3] = *(const uint32_t*)&ks[(trow + 8) * ASTH + col + 8];
        }

        // partial O over this warp's 32 s-cols: 16 rows x 64 h
        float o[8][4];
        #pragma unroll
        for (int nt = 0; nt < 8; ++nt)
            #pragma unroll
            for (int r = 0; r < 4; ++r) o[nt][r] = 0.f;

        uint2 qrh[4], vrh[4];

        for (int sb = 0; sb <= tb; ++sb) {
            const int cur = sb & 1;
            __half* qs  = qsb + cur * TILE_H;
            __half* vT  = vTb + cur * TILE_H;
            __half* qsn = qsb + (cur ^ 1) * TILE_H;
            __half* vTn = vTb + (cur ^ 1) * TILE_H;

            // prefetch next Q/V (pure fp16 copies)
            if (sb < tb) {
                const size_t s1 = (size_t)(sb + 1) * 64;
                #pragma unroll
                for (int i = 0; i < 4; ++i)
                    qrh[i] = *(const uint2*)&Qg[(s1 + qrow[i]) * HEAD + qcol[i]];
                #pragma unroll
                for (int r = 0; r < 4; ++r)
                    vrh[r] = *(const uint2*)&Vg[(s1 + lr) * HEAD + (lh + r * 16)];
            }

            // S = K . Q^T  (16 t-rows x 32 s-cols, contract over h)
            float s_c[4][4];
            #pragma unroll
            for (int nt = 0; nt < 4; ++nt)
                #pragma unroll
                for (int r = 0; r < 4; ++r) s_c[nt][r] = 0.f;
            #pragma unroll
            for (int kt = 0; kt < 4; ++kt) {
                const int col = kt * 16 + 2 * t;
                #pragma unroll
                for (int nt = 0; nt < 4; ++nt) {
                    const int srow = wn * 32 + nt * 8 + g;
                    uint32_t b0 = *(const uint32_t*)&qs[srow * ASTH + col    ];
                    uint32_t b1 = *(const uint32_t*)&qs[srow * ASTH + col + 8];
                    mma16(s_c[nt], A[kt], b0, b1);
                }
            }

            // softplus + causal mask, pack into O-mma A fragments (registers!)
            const bool diag = (sb == tb);
            uint32_t pa[2][4];
            #pragma unroll
            for (int nt = 0; nt < 4; ++nt) {
                const int sc = wn * 32 + nt * 8 + 2 * t;
                float p0 = softplus_f(s_c[nt][0] * 0.03125f);
                float p1 = softplus_f(s_c[nt][1] * 0.03125f);
                float p2 = softplus_f(s_c[nt][2] * 0.03125f);
                float p3 = softplus_f(s_c[nt][3] * 0.03125f);
                if (diag) {
                    if (sc     > trow    ) p0 = 0.f;
                    if (sc + 1 > trow    ) p1 = 0.f;
                    if (sc     > trow + 8) p2 = 0.f;
                    if (sc + 1 > trow + 8) p3 = 0.f;
                }
                const int j = nt >> 1;          // k16 group
                if ((nt & 1) == 0) { pa[j][0] = f2h2(p0, p1); pa[j][1] = f2h2(p2, p3); }
                else               { pa[j][2] = f2h2(p0, p1); pa[j][3] = f2h2(p2, p3); }
            }

            // O += P . V over this warp's 32 s-cols, all 64 h
            #pragma unroll
            for (int j = 0; j < 2; ++j) {
                const int col = wn * 32 + j * 16 + 2 * t;   // s-offset in vT
                #pragma unroll
                for (int nt = 0; nt < 8; ++nt) {
                    const int hrow = nt * 8 + g;
                    uint32_t b0 = *(const uint32_t*)&vT[hrow * ASTH + col    ];
                    uint32_t b1 = *(const uint32_t*)&vT[hrow * ASTH + col + 8];
                    mma16(o[nt], pa[j], b0, b1);
                }
            }

            // store prefetched tiles into the other buffer (its readers
            // finished before the PREVIOUS barrier -> safe)
            if (sb < tb) {
                #pragma unroll
                for (int i = 0; i < 4; ++i)
                    *(uint2*)&qsn[qrow[i] * ASTH + qcol[i]] = qrh[i];
                #pragma unroll
                for (int r = 0; r < 4; ++r) {
                    int hh = lh + r * 16;
                    __half2 p0 = *(__half2*)&vrh[r].x;
                    __half2 p1 = *(__half2*)&vrh[r].y;
                    vTn[(hh + 0) * ASTH + lr] = __low2half(p0);
                    vTn[(hh + 1) * ASTH + lr] = __high2half(p0);
                    vTn[(hh + 2) * ASTH + lr] = __low2half(p1);
                    vTn[(hh + 3) * ASTH + lr] = __high2half(p1);
                }
            }
            __syncthreads();   // single barrier per iteration
        }

        // cross-wn reduction (once per t-block): wn=1 stages, wn=0 adds+writes
        if (wn == 1) {
            #pragma unroll
            for (int nt = 0; nt < 8; ++nt) {
                const int col = nt * 8 + 2 * t;
                *(float2*)&stage[(wm * 16 + g    ) * 64 + col] = make_float2(o[nt][0], o[nt][1]);
                *(float2*)&stage[(wm * 16 + g + 8) * 64 + col] = make_float2(o[nt][2], o[nt][3]);
            }
        }
        __syncthreads();
        if (wn == 0) {
            const size_t row0 = (size_t)b * SEQ + tb * 64 + trow;
            #pragma unroll
            for (int nt = 0; nt < 8; ++nt) {
                const int col = nt * 8 + 2 * t;
                float2 s0 = *(const float2*)&stage[(wm * 16 + g    ) * 64 + col];
                float2 s1 = *(const float2*)&stage[(wm * 16 + g + 8) * 64 + col];
                *(float2*)&out[(row0    ) * HEAD + col] = make_float2(o[nt][0] + s0.x, o[nt][1] + s0.y);
                *(float2*)&out[(row0 + 8) * HEAD + col] = make_float2(o[nt][2] + s1.x, o[nt][3] + s1.y);
            }
        }
        __syncthreads();   // stage (qsb) free before next hf reuses buffers
    }
}

// ---------------------------------------------------------------------------
extern "C" void kernel_launch(void* const* d_in, const int* in_sizes, int n_in,
                              void* d_out, int out_size)
{
    const float* x  = (const float*)d_in[0];
    const float* Wk = (const float*)d_in[1];
    const float* bk = (const float*)d_in[2];
    const float* Wq = (const float*)d_in[3];
    const float* bq = (const float*)d_in[4];
    const float* Wv = (const float*)d_in[5];
    const float* bv = (const float*)d_in[6];
    float* out = (float*)d_out;

    static int init = 0;
    if (!init) {
        cudaFuncSetAttribute(attn_kernel, cudaFuncAttributeMaxDynamicSharedMemorySize, ATTN_SMEM);
        cudaFuncSetAttribute(proj_mma_kernel, cudaFuncAttributeMaxDynamicSharedMemorySize, PROJ_SMEM);
        init = 1;
    }

    dim3 wg(NEMB / 16, 3);
    wt_kernel<<<wg, 256>>>(Wk, Wq, Wv);

    proj_mma_kernel<<<MTOT / 128, 256, PROJ_SMEM>>>(x, bk, bq, bv);

    dim3 ag(NTB / 2, BATCH);
    attn_kernel<<<ag, 256, ATTN_SMEM>>>(out);
}

// round 13
// speedup vs baseline: 1.1606x; 1.0240x over previous
#include <cuda_runtime.h>
#include <cuda_fp16.h>
#include <cstdint>
#include <math.h>

#define HEAD 64
#define NEMB 1024
#define BATCH 8
#define SEQ   2048
#define MTOT  (BATCH*SEQ)   // 16384
#define NTB   (SEQ/64)      // 32 t-blocks per batch

// scratch: projected k,q,v fp16 (6.3 MB) + fp16 weights
__device__ __half g_kqv[3][MTOT][HEAD];
__device__ __half g_Wh[3][HEAD][NEMB];   // Wh[p][n][k] = half(W[p][k][n])

// D += A*B : m16n8k16 fp16 inputs, fp32 accum
__device__ __forceinline__ void mma16(float c[4], const uint32_t a[4], uint32_t b0, uint32_t b1) {
    asm volatile(
        "mma.sync.aligned.m16n8k16.row.col.f32.f16.f16.f32 "
        "{%0,%1,%2,%3}, {%4,%5,%6,%7}, {%8,%9}, {%0,%1,%2,%3};"
        : "+f"(c[0]), "+f"(c[1]), "+f"(c[2]), "+f"(c[3])
        : "r"(a[0]), "r"(a[1]), "r"(a[2]), "r"(a[3]), "r"(b0), "r"(b1));
}

__device__ __forceinline__ uint32_t f2h2(float a, float b) {
    __half2 h = __floats2half2_rn(a, b);
    return *(uint32_t*)&h;
}

// ---------------------------------------------------------------------------
// W transpose + fp16 round:  g_Wh[p][n][k] = half(W[p][k][n])
// ---------------------------------------------------------------------------
__global__ __launch_bounds__(256) void wt_kernel(
    const float* __restrict__ Wk, const float* __restrict__ Wq, const float* __restrict__ Wv)
{
    __shared__ float t[64][17];
    const float* __restrict__ W = (blockIdx.y == 0) ? Wk : ((blockIdx.y == 1) ? Wq : Wv);
    const int k0 = blockIdx.x * 16;
    const int tid = threadIdx.x;
    #pragma unroll
    for (int i = 0; i < 4; ++i) {
        int idx = i * 256 + tid;
        int kk = idx >> 6, n = idx & 63;
        t[n][kk] = W[(size_t)(k0 + kk) * HEAD + n];
    }
    __syncthreads();
    #pragma unroll
    for (int i = 0; i < 4; ++i) {
        int idx = i * 256 + tid;
        int n = idx >> 4, kk = idx & 15;
        g_Wh[blockIdx.y][n][k0 + kk] = __float2half_rn(t[n][kk]);
    }
}

// ---------------------------------------------------------------------------
// Projection via fp16 mma m16n8k16 (unchanged).
// ---------------------------------------------------------------------------
#define PST 40
#define PROJ_X_H   (128 * PST)
#define PROJ_W_H   (192 * PST)
#define PROJ_SMEM  ((2 * PROJ_X_H + 2 * PROJ_W_H) * 2)   // 51200 B

__global__ __launch_bounds__(256, 1) void proj_mma_kernel(
    const float* __restrict__ x,
    const float* __restrict__ bk, const float* __restrict__ bq, const float* __restrict__ bv)
{
    extern __shared__ __half psm[];
    __half* xsb = psm;
    __half* wsb = psm + 2 * PROJ_X_H;

    const int tid  = threadIdx.x;
    const int wid  = tid >> 5, lane = tid & 31;
    const int wm   = wid >> 1, wn = wid & 1;
    const int g    = lane >> 2, t = lane & 3;
    const int m0   = blockIdx.x * 128;

    int xrow[4], xcol[4], wrow[3], wcol[3];
    #pragma unroll
    for (int i = 0; i < 4; ++i) { int idx = i * 256 + tid; xrow[i] = idx >> 3; xcol[i] = (idx & 7) * 4; }
    #pragma unroll
    for (int i = 0; i < 3; ++i) { int idx = i * 256 + tid; wrow[i] = idx >> 2; wcol[i] = (idx & 3) * 8; }

    float c[2][12][4];
    #pragma unroll
    for (int mt = 0; mt < 2; ++mt)
        #pragma unroll
        for (int nt = 0; nt < 12; ++nt)
            #pragma unroll
            for (int r = 0; r < 4; ++r) c[mt][nt][r] = 0.f;

    uint2 xr[4];
    uint4 wr[3];

    #pragma unroll
    for (int i = 0; i < 4; ++i) {
        float4 v = *(const float4*)&x[(size_t)(m0 + xrow[i]) * NEMB + xcol[i]];
        xr[i].x = f2h2(v.x, v.y); xr[i].y = f2h2(v.z, v.w);
    }
    #pragma unroll
    for (int i = 0; i < 3; ++i)
        wr[i] = *(const uint4*)&g_Wh[wrow[i] >> 6][wrow[i] & 63][wcol[i]];
    #pragma unroll
    for (int i = 0; i < 4; ++i)
        *(uint2*)&xsb[xrow[i] * PST + xcol[i]] = xr[i];
    #pragma unroll
    for (int i = 0; i < 3; ++i)
        *(uint4*)&wsb[wrow[i] * PST + wcol[i]] = wr[i];
    __syncthreads();

    for (int ch = 0; ch < 32; ++ch) {
        const int cur = ch & 1;
        __half* xs = xsb + cur * PROJ_X_H;
        __half* ws = wsb + cur * PROJ_W_H;
        __half* xsn = xsb + (cur ^ 1) * PROJ_X_H;
        __half* wsn = wsb + (cur ^ 1) * PROJ_W_H;

        if (ch < 31) {
            const int k1 = (ch + 1) * 32;
            #pragma unroll
            for (int i = 0; i < 4; ++i) {
                float4 v = *(const float4*)&x[(size_t)(m0 + xrow[i]) * NEMB + k1 + xcol[i]];
                xr[i].x = f2h2(v.x, v.y); xr[i].y = f2h2(v.z, v.w);
            }
            #pragma unroll
            for (int i = 0; i < 3; ++i)
                wr[i] = *(const uint4*)&g_Wh[wrow[i] >> 6][wrow[i] & 63][k1 + wcol[i]];
        }

        uint32_t A[2][2][4];
        #pragma unroll
        for (int mt = 0; mt < 2; ++mt) {
            const int row = wm * 32 + mt * 16 + g;
            #pragma unroll
            for (int kt = 0; kt < 2; ++kt) {
                const int col = kt * 16 + 2 * t;
                A[mt][kt][0] = *(const uint32_t*)&xs[(row    ) * PST + col    ];
                A[mt][kt][1] = *(const uint32_t*)&xs[(row + 8) * PST + col    ];
                A[mt][kt][2] = *(const uint32_t*)&xs[(row    ) * PST + col + 8];
                A[mt][kt][3] = *(const uint32_t*)&xs[(row + 8) * PST + col + 8];
            }
        }
        #pragma unroll
        for (int kt = 0; kt < 2; ++kt) {
            #pragma unroll
            for (int nt = 0; nt < 12; ++nt) {
                const int ng = wn * 96 + nt * 8 + g;
                const int col = kt * 16 + 2 * t;
                uint32_t b0 = *(const uint32_t*)&ws[ng * PST + col    ];
                uint32_t b1 = *(const uint32_t*)&ws[ng * PST + col + 8];
                mma16(c[0][nt], A[0][kt], b0, b1);
                mma16(c[1][nt], A[1][kt], b0, b1);
            }
        }

        if (ch < 31) {
            #pragma unroll
            for (int i = 0; i < 4; ++i)
                *(uint2*)&xsn[xrow[i] * PST + xcol[i]] = xr[i];
            #pragma unroll
            for (int i = 0; i < 3; ++i)
                *(uint4*)&wsn[wrow[i] * PST + wcol[i]] = wr[i];
        }
        __syncthreads();
    }

    const float* biases[3] = {bk, bq, bv};
    #pragma unroll
    for (int nt = 0; nt < 12; ++nt) {
        const int ng0 = wn * 96 + nt * 8;
        const int p = ng0 >> 6;
        const int n = (ng0 & 63) + 2 * t;
        const float* __restrict__ bias = biases[p];
        const float b0 = bias[n], b1 = bias[n + 1];
        #pragma unroll
        for (int mt = 0; mt < 2; ++mt) {
            const int row = m0 + wm * 32 + mt * 16 + g;
            *(uint32_t*)&g_kqv[p][row    ][n] = f2h2(c[mt][nt][0] + b0, c[mt][nt][1] + b1);
            *(uint32_t*)&g_kqv[p][row + 8][n] = f2h2(c[mt][nt][2] + b0, c[mt][nt][3] + b1);
        }
    }
}

// ---------------------------------------------------------------------------
// Attention, P-in-registers + PAIRED s-blocks (2 per stage, 4 smem slots).
// Per stage: S0,S1 mma -> softplus0,1 (interleaved MUFU chains) -> O0,O1 mma
// -> store prefetched pair -> ONE barrier. Diagonal only possible on blk 1
// of a pair or the peeled odd block.
// ---------------------------------------------------------------------------
#define ASTH 72
#define TILE_H (64 * ASTH)
#define ATTN_SMEM (9 * TILE_H * 2)          // ks + 4*qs + 4*vT = 82944 B

__device__ __forceinline__ float softplus_f(float x) {
    return fmaxf(x, 0.f) + __logf(1.f + __expf(-fabsf(x)));
}

__global__ __launch_bounds__(256, 1) void attn_kernel(float* __restrict__ out)
{
    extern __shared__ __half smh[];
    __half* ks  = smh;                       // [64][ASTH]  K tile [t][h]
    __half* qsb = smh + TILE_H;              // 4 x Q tiles [s][h]
    __half* vTb = smh + 5 * TILE_H;          // 4 x V transposed [h][s]
    float*  stage = (float*)qsb;             // epilogue staging (16 KB, reused)

    const int b    = blockIdx.y;
    const int tid  = threadIdx.x;
    const int wid  = tid >> 5, lane = tid & 31;
    const int wm   = wid >> 1, wn = wid & 1;
    const int g    = lane >> 2, t = lane & 3;
    const int lr   = tid & 63;               // V loader row (s)
    const int lh   = (tid >> 6) * 4;         // V loader col base (h)
    const int trow = wm * 16 + g;

    int qrow[4], qcol[4];
    #pragma unroll
    for (int i = 0; i < 4; ++i) { int idx = i * 256 + tid; qrow[i] = idx >> 4; qcol[i] = (idx & 15) * 4; }

    const __half* __restrict__ Kg = &g_kqv[0][(size_t)b * SEQ][0];
    const __half* __restrict__ Qg = &g_kqv[1][(size_t)b * SEQ][0];
    const __half* __restrict__ Vg = &g_kqv[2][(size_t)b * SEQ][0];

    for (int hf = 0; hf < 2; ++hf) {
        const int tb = hf ? (NTB - 1 - (int)blockIdx.x) : (int)blockIdx.x;
        const int nblocks = tb + 1;
        const int npairs  = nblocks >> 1;

        // K tile [t][h]
        #pragma unroll
        for (int i = 0; i < 4; ++i) {
            uint2 u = *(const uint2*)&Kg[(size_t)(tb * 64 + qrow[i]) * HEAD + qcol[i]];
            *(uint2*)&ks[qrow[i] * ASTH + qcol[i]] = u;
        }

        // prologue: blocks 0 (and 1 if present) into slots 0,1
        #pragma unroll
        for (int blk = 0; blk < 2; ++blk) {
            if (blk > tb) break;
            __half* qs = qsb + blk * TILE_H;
            __half* vT = vTb + blk * TILE_H;
            const size_t s0 = (size_t)blk * 64;
            #pragma unroll
            for (int i = 0; i < 4; ++i) {
                uint2 u = *(const uint2*)&Qg[(s0 + qrow[i]) * HEAD + qcol[i]];
                *(uint2*)&qs[qrow[i] * ASTH + qcol[i]] = u;
            }
            #pragma unroll
            for (int r = 0; r < 4; ++r) {
                int hh = lh + r * 16;
                uint2 u = *(const uint2*)&Vg[(s0 + lr) * HEAD + hh];
                __half2 p0 = *(__half2*)&u.x;
                __half2 p1 = *(__half2*)&u.y;
                vT[(hh + 0) * ASTH + lr] = __low2half(p0);
                vT[(hh + 1) * ASTH + lr] = __high2half(p0);
                vT[(hh + 2) * ASTH + lr] = __low2half(p1);
                vT[(hh + 3) * ASTH + lr] = __high2half(p1);
            }
        }
        __syncthreads();

        // K A-fragments, resident across the s-loop
        uint32_t A[4][4];
        #pragma unroll
        for (int kt = 0; kt < 4; ++kt) {
            const int col = kt * 16 + 2 * t;
            A[kt][0] = *(const uint32_t*)&ks[(trow    ) * ASTH + col    ];
            A[kt][1] = *(const uint32_t*)&ks[(trow + 8) * ASTH + col    ];
            A[kt][2] = *(const uint32_t*)&ks[(trow    ) * ASTH + col + 8];
            A[kt][3] = *(const uint32_t*)&ks[(trow + 8) * ASTH + col + 8];
        }

        // partial O over this warp's 32 s-cols: 16 rows x 64 h
        float o[8][4];
        #pragma unroll
        for (int nt = 0; nt < 8; ++nt)
            #pragma unroll
            for (int r = 0; r < 4; ++r) o[nt][r] = 0.f;

        uint2 qrh[2][4], vrh[2][4];

        for (int p = 0; p < npairs; ++p) {
            const int base  = (p & 1) * 2;
            const int nbase = ((p + 1) & 1) * 2;
            const int b1 = 2 * p + 1;

            // prefetch blocks 2p+2, 2p+3 into registers
            const int pf0 = 2 * p + 2, pf1 = 2 * p + 3;
            const bool v0 = pf0 <= tb, v1 = pf1 <= tb;
            if (v0) {
                const size_t s1 = (size_t)pf0 * 64;
                #pragma unroll
                for (int i = 0; i < 4; ++i)
                    qrh[0][i] = *(const uint2*)&Qg[(s1 + qrow[i]) * HEAD + qcol[i]];
                #pragma unroll
                for (int r = 0; r < 4; ++r)
                    vrh[0][r] = *(const uint2*)&Vg[(s1 + lr) * HEAD + (lh + r * 16)];
            }
            if (v1) {
                const size_t s1 = (size_t)pf1 * 64;
                #pragma unroll
                for (int i = 0; i < 4; ++i)
                    qrh[1][i] = *(const uint2*)&Qg[(s1 + qrow[i]) * HEAD + qcol[i]];
                #pragma unroll
                for (int r = 0; r < 4; ++r)
                    vrh[1][r] = *(const uint2*)&Vg[(s1 + lr) * HEAD + (lh + r * 16)];
            }

            // S-phase for both blocks (independent chains)
            float s_c[2][4][4];
            #pragma unroll
            for (int blk = 0; blk < 2; ++blk)
                #pragma unroll
                for (int nt = 0; nt < 4; ++nt)
                    #pragma unroll
                    for (int r = 0; r < 4; ++r) s_c[blk][nt][r] = 0.f;
            #pragma unroll
            for (int blk = 0; blk < 2; ++blk) {
                const __half* qs = qsb + (base + blk) * TILE_H;
                #pragma unroll
                for (int kt = 0; kt < 4; ++kt) {
                    const int col = kt * 16 + 2 * t;
                    #pragma unroll
                    for (int nt = 0; nt < 4; ++nt) {
                        const int srow = wn * 32 + nt * 8 + g;
                        uint32_t b0 = *(const uint32_t*)&qs[srow * ASTH + col    ];
                        uint32_t b1r = *(const uint32_t*)&qs[srow * ASTH + col + 8];
                        mma16(s_c[blk][nt], A[kt], b0, b1r);
                    }
                }
            }

            // softplus both blocks (MUFU chains interleave); diag only blk 1
            uint32_t pa[2][2][4];
            #pragma unroll
            for (int blk = 0; blk < 2; ++blk) {
                const bool diag = (blk == 1) && (b1 == tb);
                #pragma unroll
                for (int nt = 0; nt < 4; ++nt) {
                    const int sc = wn * 32 + nt * 8 + 2 * t;
                    float p0 = softplus_f(s_c[blk][nt][0] * 0.03125f);
                    float p1 = softplus_f(s_c[blk][nt][1] * 0.03125f);
                    float p2 = softplus_f(s_c[blk][nt][2] * 0.03125f);
                    float p3 = softplus_f(s_c[blk][nt][3] * 0.03125f);
                    if (diag) {
                        if (sc     > trow    ) p0 = 0.f;
                        if (sc + 1 > trow    ) p1 = 0.f;
                        if (sc     > trow + 8) p2 = 0.f;
                        if (sc + 1 > trow + 8) p3 = 0.f;
                    }
                    const int j = nt >> 1;
                    if ((nt & 1) == 0) { pa[blk][j][0] = f2h2(p0, p1); pa[blk][j][1] = f2h2(p2, p3); }
                    else               { pa[blk][j][2] = f2h2(p0, p1); pa[blk][j][3] = f2h2(p2, p3); }
                }
            }

            // O-phase for both blocks
            #pragma unroll
            for (int blk = 0; blk < 2; ++blk) {
                const __half* vT = vTb + (base + blk) * TILE_H;
                #pragma unroll
                for (int j = 0; j < 2; ++j) {
                    const int col = wn * 32 + j * 16 + 2 * t;
                    #pragma unroll
                    for (int nt = 0; nt < 8; ++nt) {
                        const int hrow = nt * 8 + g;
                        uint32_t b0 = *(const uint32_t*)&vT[hrow * ASTH + col    ];
                        uint32_t b1r = *(const uint32_t*)&vT[hrow * ASTH + col + 8];
                        mma16(o[nt], pa[blk][j], b0, b1r);
                    }
                }
            }

            // store prefetched pair into the other slot pair (readers done
            // before previous barrier), then one barrier
            if (v0) {
                __half* qsn = qsb + nbase * TILE_H;
                __half* vTn = vTb + nbase * TILE_H;
                #pragma unroll
                for (int i = 0; i < 4; ++i)
                    *(uint2*)&qsn[qrow[i] * ASTH + qcol[i]] = qrh[0][i];
                #pragma unroll
                for (int r = 0; r < 4; ++r) {
                    int hh = lh + r * 16;
                    __half2 p0 = *(__half2*)&vrh[0][r].x;
                    __half2 p1 = *(__half2*)&vrh[0][r].y;
                    vTn[(hh + 0) * ASTH + lr] = __low2half(p0);
                    vTn[(hh + 1) * ASTH + lr] = __high2half(p0);
                    vTn[(hh + 2) * ASTH + lr] = __low2half(p1);
                    vTn[(hh + 3) * ASTH + lr] = __high2half(p1);
                }
            }
            if (v1) {
                __half* qsn = qsb + (nbase + 1) * TILE_H;
                __half* vTn = vTb + (nbase + 1) * TILE_H;
                #pragma unroll
                for (int i = 0; i < 4; ++i)
                    *(uint2*)&qsn[qrow[i] * ASTH + qcol[i]] = qrh[1][i];
                #pragma unroll
                for (int r = 0; r < 4; ++r) {
                    int hh = lh + r * 16;
                    __half2 p0 = *(__half2*)&vrh[1][r].x;
                    __half2 p1 = *(__half2*)&vrh[1][r].y;
                    vTn[(hh + 0) * ASTH + lr] = __low2half(p0);
                    vTn[(hh + 1) * ASTH + lr] = __high2half(p0);
                    vTn[(hh + 2) * ASTH + lr] = __low2half(p1);
                    vTn[(hh + 3) * ASTH + lr] = __high2half(p1);
                }
            }
            __syncthreads();
        }

        // peeled odd block (always the diagonal, sb = tb)
        if (nblocks & 1) {
            const int base = (npairs & 1) * 2;
            const __half* qs = qsb + base * TILE_H;
            const __half* vT = vTb + base * TILE_H;

            float s_c[4][4];
            #pragma unroll
            for (int nt = 0; nt < 4; ++nt)
                #pragma unroll
                for (int r = 0; r < 4; ++r) s_c[nt][r] = 0.f;
            #pragma unroll
            for (int kt = 0; kt < 4; ++kt) {
                const int col = kt * 16 + 2 * t;
                #pragma unroll
                for (int nt = 0; nt < 4; ++nt) {
                    const int srow = wn * 32 + nt * 8 + g;
                    uint32_t b0 = *(const uint32_t*)&qs[srow * ASTH + col    ];
                    uint32_t b1r = *(const uint32_t*)&qs[srow * ASTH + col + 8];
                    mma16(s_c[nt], A[kt], b0, b1r);
                }
            }

            uint32_t pa[2][4];
            #pragma unroll
            for (int nt = 0; nt < 4; ++nt) {
                const int sc = wn * 32 + nt * 8 + 2 * t;
                float p0 = softplus_f(s_c[nt][0] * 0.03125f);
                float p1 = softplus_f(s_c[nt][1] * 0.03125f);
                float p2 = softplus_f(s_c[nt][2] * 0.03125f);
                float p3 = softplus_f(s_c[nt][3] * 0.03125f);
                if (sc     > trow    ) p0 = 0.f;
                if (sc + 1 > trow    ) p1 = 0.f;
                if (sc     > trow + 8) p2 = 0.f;
                if (sc + 1 > trow + 8) p3 = 0.f;
                const int j = nt >> 1;
                if ((nt & 1) == 0) { pa[j][0] = f2h2(p0, p1); pa[j][1] = f2h2(p2, p3); }
                else               { pa[j][2] = f2h2(p0, p1); pa[j][3] = f2h2(p2, p3); }
            }

            #pragma unroll
            for (int j = 0; j < 2; ++j) {
                const int col = wn * 32 + j * 16 + 2 * t;
                #pragma unroll
                for (int nt = 0; nt < 8; ++nt) {
                    const int hrow = nt * 8 + g;
                    uint32_t b0 = *(const uint32_t*)&vT[hrow * ASTH + col    ];
                    uint32_t b1r = *(const uint32_t*)&vT[hrow * ASTH + col + 8];
                    mma16(o[nt], pa[j], b0, b1r);
                }
            }
            __syncthreads();   // all reads done before stage reuses qs slots
        }

        // cross-wn reduction (once per t-block): wn=1 stages, wn=0 adds+writes
        if (wn == 1) {
            #pragma unroll
            for (int nt = 0; nt < 8; ++nt) {
                const int col = nt * 8 + 2 * t;
                *(float2*)&stage[(wm * 16 + g    ) * 64 + col] = make_float2(o[nt][0], o[nt][1]);
                *(float2*)&stage[(wm * 16 + g + 8) * 64 + col] = make_float2(o[nt][2], o[nt][3]);
            }
        }
        __syncthreads();
        if (wn == 0) {
            const size_t row0 = (size_t)b * SEQ + tb * 64 + trow;
            #pragma unroll
            for (int nt = 0; nt < 8; ++nt) {
                const int col = nt * 8 + 2 * t;
                float2 s0 = *(const float2*)&stage[(wm * 16 + g    ) * 64 + col];
                float2 s1 = *(const float2*)&stage[(wm * 16 + g + 8) * 64 + col];
                *(float2*)&out[(row0    ) * HEAD + col] = make_float2(o[nt][0] + s0.x, o[nt][1] + s0.y);
                *(float2*)&out[(row0 + 8) * HEAD + col] = make_float2(o[nt][2] + s1.x, o[nt][3] + s1.y);
            }
        }
        __syncthreads();   // stage free before next hf reuses buffers
    }
}

// ---------------------------------------------------------------------------
extern "C" void kernel_launch(void* const* d_in, const int* in_sizes, int n_in,
                              void* d_out, int out_size)
{
    const float* x  = (const float*)d_in[0];
    const float* Wk = (const float*)d_in[1];
    const float* bk = (const float*)d_in[2];
    const float* Wq = (const float*)d_in[3];
    const float* bq = (const float*)d_in[4];
    const float* Wv = (const float*)d_in[5];
    const float* bv = (const float*)d_in[6];
    float* out = (float*)d_out;

    static int init = 0;
    if (!init) {
        cudaFuncSetAttribute(attn_kernel, cudaFuncAttributeMaxDynamicSharedMemorySize, ATTN_SMEM);
        cudaFuncSetAttribute(proj_mma_kernel, cudaFuncAttributeMaxDynamicSharedMemorySize, PROJ_SMEM);
        init = 1;
    }

    dim3 wg(NEMB / 16, 3);
    wt_kernel<<<wg, 256>>>(Wk, Wq, Wv);

    proj_mma_kernel<<<MTOT / 128, 256, PROJ_SMEM>>>(x, bk, bq, bv);

    dim3 ag(NTB / 2, BATCH);
    attn_kernel<<<ag, 256, ATTN_SMEM>>>(out);
}

// round 14
// speedup vs baseline: 1.4311x; 1.2331x over previous
#include <cuda_runtime.h>
#include <cuda_fp16.h>
#include <cstdint>
#include <math.h>

#define HEAD 64
#define NEMB 1024
#define BATCH 8
#define SEQ   2048
#define MTOT  (BATCH*SEQ)   // 16384
#define NTB   (SEQ/64)      // 32 t-blocks per batch

// scratch: projected k,q,v fp16 (6.3 MB) + fp16 weights
__device__ __half g_kqv[3][MTOT][HEAD];
__device__ __half g_Wh[3][HEAD][NEMB];   // Wh[p][n][k] = half(W[p][k][n])

// D += A*B : m16n8k16 fp16 inputs, fp32 accum
__device__ __forceinline__ void mma16(float c[4], const uint32_t a[4], uint32_t b0, uint32_t b1) {
    asm volatile(
        "mma.sync.aligned.m16n8k16.row.col.f32.f16.f16.f32 "
        "{%0,%1,%2,%3}, {%4,%5,%6,%7}, {%8,%9}, {%0,%1,%2,%3};"
        : "+f"(c[0]), "+f"(c[1]), "+f"(c[2]), "+f"(c[3])
        : "r"(a[0]), "r"(a[1]), "r"(a[2]), "r"(a[3]), "r"(b0), "r"(b1));
}

__device__ __forceinline__ void ldsm4(uint32_t r[4], uint32_t a) {
    asm volatile("ldmatrix.sync.aligned.m8n8.x4.shared.b16 {%0,%1,%2,%3}, [%4];"
        : "=r"(r[0]), "=r"(r[1]), "=r"(r[2]), "=r"(r[3]) : "r"(a));
}
__device__ __forceinline__ void ldsm4t(uint32_t r[4], uint32_t a) {
    asm volatile("ldmatrix.sync.aligned.m8n8.x4.trans.shared.b16 {%0,%1,%2,%3}, [%4];"
        : "=r"(r[0]), "=r"(r[1]), "=r"(r[2]), "=r"(r[3]) : "r"(a));
}

__device__ __forceinline__ uint32_t f2h2(float a, float b) {
    __half2 h = __floats2half2_rn(a, b);
    return *(uint32_t*)&h;
}
__device__ __forceinline__ uint32_t smem32(const void* p) {
    return (uint32_t)__cvta_generic_to_shared(p);
}

// ---------------------------------------------------------------------------
// W transpose + fp16 round:  g_Wh[p][n][k] = half(W[p][k][n])
// ---------------------------------------------------------------------------
__global__ __launch_bounds__(256) void wt_kernel(
    const float* __restrict__ Wk, const float* __restrict__ Wq, const float* __restrict__ Wv)
{
    __shared__ float t[64][17];
    const float* __restrict__ W = (blockIdx.y == 0) ? Wk : ((blockIdx.y == 1) ? Wq : Wv);
    const int k0 = blockIdx.x * 16;
    const int tid = threadIdx.x;
    #pragma unroll
    for (int i = 0; i < 4; ++i) {
        int idx = i * 256 + tid;
        int kk = idx >> 6, n = idx & 63;
        t[n][kk] = W[(size_t)(k0 + kk) * HEAD + n];
    }
    __syncthreads();
    #pragma unroll
    for (int i = 0; i < 4; ++i) {
        int idx = i * 256 + tid;
        int n = idx >> 4, kk = idx & 15;
        g_Wh[blockIdx.y][n][k0 + kk] = __float2half_rn(t[n][kk]);
    }
}

// ---------------------------------------------------------------------------
// Projection via fp16 mma + ldmatrix. CTA: 128(m) x 192(n), K chunk 32,
// ping-pong buffers, 1 barrier/chunk. Row stride 40 halves (80 B).
// ---------------------------------------------------------------------------
#define PST 40
#define PSTB 80
#define PROJ_X_H   (128 * PST)
#define PROJ_W_H   (192 * PST)
#define PROJ_SMEM  ((2 * PROJ_X_H + 2 * PROJ_W_H) * 2)   // 51200 B

__global__ __launch_bounds__(256, 1) void proj_mma_kernel(
    const float* __restrict__ x,
    const float* __restrict__ bk, const float* __restrict__ bq, const float* __restrict__ bv)
{
    extern __shared__ __half psm[];
    __half* xsb = psm;
    __half* wsb = psm + 2 * PROJ_X_H;

    const int tid  = threadIdx.x;
    const int wid  = tid >> 5, lane = tid & 31;
    const int wm   = wid >> 1, wn = wid & 1;
    const int g    = lane >> 2, t = lane & 3;
    const int m0   = blockIdx.x * 128;
    const int lm   = lane >> 3, lrr = lane & 7;     // ldmatrix lane decomposition

    const uint32_t psm32 = smem32(psm);
    const uint32_t xs32[2] = { psm32, psm32 + PROJ_X_H * 2 };
    const uint32_t ws32[2] = { psm32 + 4 * PROJ_X_H, psm32 + 4 * PROJ_X_H + PROJ_W_H * 2 };

    // ldmatrix per-lane offsets (bytes)
    const uint32_t paoff = (uint32_t)((wm * 32 + (lm & 1) * 8 + lrr) * PSTB + (lm >> 1) * 16);
    const uint32_t pboff = (uint32_t)((wn * 96 + (lm >> 1) * 8 + lrr) * PSTB + (lm & 1) * 16);

    int xrow[4], xcol[4], wrow[3], wcol[3];
    #pragma unroll
    for (int i = 0; i < 4; ++i) { int idx = i * 256 + tid; xrow[i] = idx >> 3; xcol[i] = (idx & 7) * 4; }
    #pragma unroll
    for (int i = 0; i < 3; ++i) { int idx = i * 256 + tid; wrow[i] = idx >> 2; wcol[i] = (idx & 3) * 8; }

    float c[2][12][4];
    #pragma unroll
    for (int mt = 0; mt < 2; ++mt)
        #pragma unroll
        for (int nt = 0; nt < 12; ++nt)
            #pragma unroll
            for (int r = 0; r < 4; ++r) c[mt][nt][r] = 0.f;

    uint2 xr[4];
    uint4 wr[3];

    #pragma unroll
    for (int i = 0; i < 4; ++i) {
        float4 v = *(const float4*)&x[(size_t)(m0 + xrow[i]) * NEMB + xcol[i]];
        xr[i].x = f2h2(v.x, v.y); xr[i].y = f2h2(v.z, v.w);
    }
    #pragma unroll
    for (int i = 0; i < 3; ++i)
        wr[i] = *(const uint4*)&g_Wh[wrow[i] >> 6][wrow[i] & 63][wcol[i]];
    #pragma unroll
    for (int i = 0; i < 4; ++i)
        *(uint2*)&xsb[xrow[i] * PST + xcol[i]] = xr[i];
    #pragma unroll
    for (int i = 0; i < 3; ++i)
        *(uint4*)&wsb[wrow[i] * PST + wcol[i]] = wr[i];
    __syncthreads();

    for (int ch = 0; ch < 32; ++ch) {
        const int cur = ch & 1;
        __half* xsn = xsb + (cur ^ 1) * PROJ_X_H;
        __half* wsn = wsb + (cur ^ 1) * PROJ_W_H;

        if (ch < 31) {
            const int k1 = (ch + 1) * 32;
            #pragma unroll
            for (int i = 0; i < 4; ++i) {
                float4 v = *(const float4*)&x[(size_t)(m0 + xrow[i]) * NEMB + k1 + xcol[i]];
                xr[i].x = f2h2(v.x, v.y); xr[i].y = f2h2(v.z, v.w);
            }
            #pragma unroll
            for (int i = 0; i < 3; ++i)
                wr[i] = *(const uint4*)&g_Wh[wrow[i] >> 6][wrow[i] & 63][k1 + wcol[i]];
        }

        // A fragments via ldmatrix: (mt, kt)
        uint32_t A[2][2][4];
        #pragma unroll
        for (int mt = 0; mt < 2; ++mt)
            #pragma unroll
            for (int kt = 0; kt < 2; ++kt)
                ldsm4(A[mt][kt], xs32[cur] + paoff + (uint32_t)(mt * 16 * PSTB + kt * 32));

        #pragma unroll
        for (int kt = 0; kt < 2; ++kt) {
            #pragma unroll
            for (int p2 = 0; p2 < 6; ++p2) {
                uint32_t B4[4];
                ldsm4(B4, ws32[cur] + pboff + (uint32_t)(p2 * 16 * PSTB + kt * 32));
                mma16(c[0][2 * p2    ], A[0][kt], B4[0], B4[1]);
                mma16(c[0][2 * p2 + 1], A[0][kt], B4[2], B4[3]);
                mma16(c[1][2 * p2    ], A[1][kt], B4[0], B4[1]);
                mma16(c[1][2 * p2 + 1], A[1][kt], B4[2], B4[3]);
            }
        }

        if (ch < 31) {
            #pragma unroll
            for (int i = 0; i < 4; ++i)
                *(uint2*)&xsn[xrow[i] * PST + xcol[i]] = xr[i];
            #pragma unroll
            for (int i = 0; i < 3; ++i)
                *(uint4*)&wsn[wrow[i] * PST + wcol[i]] = wr[i];
        }
        __syncthreads();
    }

    const float* biases[3] = {bk, bq, bv};
    #pragma unroll
    for (int nt = 0; nt < 12; ++nt) {
        const int ng0 = wn * 96 + nt * 8;
        const int p = ng0 >> 6;
        const int n = (ng0 & 63) + 2 * t;
        const float* __restrict__ bias = biases[p];
        const float b0 = bias[n], b1 = bias[n + 1];
        #pragma unroll
        for (int mt = 0; mt < 2; ++mt) {
            const int row = m0 + wm * 32 + mt * 16 + g;
            *(uint32_t*)&g_kqv[p][row    ][n] = f2h2(c[mt][nt][0] + b0, c[mt][nt][1] + b1);
            *(uint32_t*)&g_kqv[p][row + 8][n] = f2h2(c[mt][nt][2] + b0, c[mt][nt][3] + b1);
        }
    }
}

// ---------------------------------------------------------------------------
// Attention: P-in-registers + paired s-blocks + ldmatrix fragments.
// V kept in NATURAL [s][h] layout; O-phase B via ldmatrix.trans.
// Row stride 72 halves (144 B): LDSM rows cover all 32 banks (conflict-free).
// ---------------------------------------------------------------------------
#define ASTH 72
#define ASTB 144
#define TILE_H (64 * ASTH)
#define ATTN_SMEM (9 * TILE_H * 2)          // ks + 4*qs + 4*vs = 82944 B

__device__ __forceinline__ float softplus_f(float x) {
    return __logf(1.f + __expf(x));         // |x| <~ 17 here: safe, exact enough
}

__global__ __launch_bounds__(256, 1) void attn_kernel(float* __restrict__ out)
{
    extern __shared__ __half smh[];
    __half* ks  = smh;                       // [64][ASTH]  K tile [t][h]
    __half* qsb = smh + TILE_H;              // 4 x Q tiles [s][h]
    __half* vsb = smh + 5 * TILE_H;          // 4 x V tiles [s][h] (natural)
    float*  stage = (float*)qsb;             // epilogue staging (16 KB, reused)

    const int b    = blockIdx.y;
    const int tid  = threadIdx.x;
    const int wid  = tid >> 5, lane = tid & 31;
    const int wm   = wid >> 1, wn = wid & 1;
    const int g    = lane >> 2, t = lane & 3;
    const int lm   = lane >> 3, lrr = lane & 7;
    const int trow = wm * 16 + g;

    const uint32_t sm32 = smem32(smh);
    const uint32_t ks32 = sm32;
    uint32_t qs32[4], vs32[4];
    #pragma unroll
    for (int s = 0; s < 4; ++s) {
        qs32[s] = sm32 + (uint32_t)((1 + s) * TILE_H * 2);
        vs32[s] = sm32 + (uint32_t)((5 + s) * TILE_H * 2);
    }

    // ldmatrix per-lane offsets (bytes)
    const uint32_t kaoff = (uint32_t)((wm * 16 + (lm & 1) * 8 + lrr) * ASTB + (lm >> 1) * 16);
    const uint32_t qboff = (uint32_t)((wn * 32 + (lm >> 1) * 8 + lrr) * ASTB + (lm & 1) * 16);
    const uint32_t vboff = (uint32_t)(((lm & 1) * 8 + lrr) * ASTB + (lm >> 1) * 16);

    int qrow[4], qcol[4];
    #pragma unroll
    for (int i = 0; i < 4; ++i) { int idx = i * 256 + tid; qrow[i] = idx >> 4; qcol[i] = (idx & 15) * 4; }

    const __half* __restrict__ Kg = &g_kqv[0][(size_t)b * SEQ][0];
    const __half* __restrict__ Qg = &g_kqv[1][(size_t)b * SEQ][0];
    const __half* __restrict__ Vg = &g_kqv[2][(size_t)b * SEQ][0];

    for (int hf = 0; hf < 2; ++hf) {
        const int tb = hf ? (NTB - 1 - (int)blockIdx.x) : (int)blockIdx.x;
        const int nblocks = tb + 1;
        const int npairs  = nblocks >> 1;

        // K tile [t][h]
        #pragma unroll
        for (int i = 0; i < 4; ++i) {
            uint2 u = *(const uint2*)&Kg[(size_t)(tb * 64 + qrow[i]) * HEAD + qcol[i]];
            *(uint2*)&ks[qrow[i] * ASTH + qcol[i]] = u;
        }

        // prologue: blocks 0 (and 1 if present) into slots 0,1
        #pragma unroll
        for (int blk = 0; blk < 2; ++blk) {
            if (blk > tb) break;
            __half* qs = qsb + blk * TILE_H;
            __half* vs = vsb + blk * TILE_H;
            const size_t s0 = (size_t)blk * 64;
            #pragma unroll
            for (int i = 0; i < 4; ++i) {
                *(uint2*)&qs[qrow[i] * ASTH + qcol[i]] =
                    *(const uint2*)&Qg[(s0 + qrow[i]) * HEAD + qcol[i]];
                *(uint2*)&vs[qrow[i] * ASTH + qcol[i]] =
                    *(const uint2*)&Vg[(s0 + qrow[i]) * HEAD + qcol[i]];
            }
        }
        __syncthreads();

        // K A-fragments via ldmatrix, resident across the s-loop
        uint32_t A[4][4];
        #pragma unroll
        for (int kt = 0; kt < 4; ++kt)
            ldsm4(A[kt], ks32 + kaoff + (uint32_t)(kt * 32));

        float o[8][4];
        #pragma unroll
        for (int nt = 0; nt < 8; ++nt)
            #pragma unroll
            for (int r = 0; r < 4; ++r) o[nt][r] = 0.f;

        uint2 qrh[2][4], vrh[2][4];

        for (int p = 0; p < npairs; ++p) {
            const int base  = (p & 1) * 2;
            const int nbase = ((p + 1) & 1) * 2;
            const int b1 = 2 * p + 1;

            const int pf0 = 2 * p + 2, pf1 = 2 * p + 3;
            const bool v0 = pf0 <= tb, v1 = pf1 <= tb;
            if (v0) {
                const size_t s1 = (size_t)pf0 * 64;
                #pragma unroll
                for (int i = 0; i < 4; ++i) {
                    qrh[0][i] = *(const uint2*)&Qg[(s1 + qrow[i]) * HEAD + qcol[i]];
                    vrh[0][i] = *(const uint2*)&Vg[(s1 + qrow[i]) * HEAD + qcol[i]];
                }
            }
            if (v1) {
                const size_t s1 = (size_t)pf1 * 64;
                #pragma unroll
                for (int i = 0; i < 4; ++i) {
                    qrh[1][i] = *(const uint2*)&Qg[(s1 + qrow[i]) * HEAD + qcol[i]];
                    vrh[1][i] = *(const uint2*)&Vg[(s1 + qrow[i]) * HEAD + qcol[i]];
                }
            }

            // S-phase for both blocks
            float s_c[2][4][4];
            #pragma unroll
            for (int blk = 0; blk < 2; ++blk)
                #pragma unroll
                for (int nt = 0; nt < 4; ++nt)
                    #pragma unroll
                    for (int r = 0; r < 4; ++r) s_c[blk][nt][r] = 0.f;
            #pragma unroll
            for (int blk = 0; blk < 2; ++blk) {
                const uint32_t qb = qs32[base + blk];
                #pragma unroll
                for (int kt = 0; kt < 4; ++kt) {
                    #pragma unroll
                    for (int p2 = 0; p2 < 2; ++p2) {
                        uint32_t B4[4];
                        ldsm4(B4, qb + qboff + (uint32_t)(p2 * 16 * ASTB + kt * 32));
                        mma16(s_c[blk][2 * p2    ], A[kt], B4[0], B4[1]);
                        mma16(s_c[blk][2 * p2 + 1], A[kt], B4[2], B4[3]);
                    }
                }
            }

            // softplus both blocks; diag only possible on blk 1
            uint32_t pa[2][2][4];
            #pragma unroll
            for (int blk = 0; blk < 2; ++blk) {
                const bool diag = (blk == 1) && (b1 == tb);
                #pragma unroll
                for (int nt = 0; nt < 4; ++nt) {
                    const int sc = wn * 32 + nt * 8 + 2 * t;
                    float p0 = softplus_f(s_c[blk][nt][0] * 0.03125f);
                    float p1 = softplus_f(s_c[blk][nt][1] * 0.03125f);
                    float p2 = softplus_f(s_c[blk][nt][2] * 0.03125f);
                    float p3 = softplus_f(s_c[blk][nt][3] * 0.03125f);
                    if (diag) {
                        if (sc     > trow    ) p0 = 0.f;
                        if (sc + 1 > trow    ) p1 = 0.f;
                        if (sc     > trow + 8) p2 = 0.f;
                        if (sc + 1 > trow + 8) p3 = 0.f;
                    }
                    const int j = nt >> 1;
                    if ((nt & 1) == 0) { pa[blk][j][0] = f2h2(p0, p1); pa[blk][j][1] = f2h2(p2, p3); }
                    else               { pa[blk][j][2] = f2h2(p0, p1); pa[blk][j][3] = f2h2(p2, p3); }
                }
            }

            // O-phase for both blocks (B via ldmatrix.trans from natural V)
            #pragma unroll
            for (int blk = 0; blk < 2; ++blk) {
                const uint32_t vb = vs32[base + blk];
                #pragma unroll
                for (int j = 0; j < 2; ++j) {
                    const uint32_t vjb = vb + (uint32_t)((wn * 32 + j * 16) * ASTB) + vboff;
                    #pragma unroll
                    for (int q = 0; q < 4; ++q) {
                        uint32_t B4[4];
                        ldsm4t(B4, vjb + (uint32_t)(q * 32));
                        mma16(o[2 * q    ], pa[blk][j], B4[0], B4[1]);
                        mma16(o[2 * q + 1], pa[blk][j], B4[2], B4[3]);
                    }
                }
            }

            // store prefetched pair into the other slot pair, then one barrier
            if (v0) {
                __half* qsn = qsb + nbase * TILE_H;
                __half* vsn = vsb + nbase * TILE_H;
                #pragma unroll
                for (int i = 0; i < 4; ++i) {
                    *(uint2*)&qsn[qrow[i] * ASTH + qcol[i]] = qrh[0][i];
                    *(uint2*)&vsn[qrow[i] * ASTH + qcol[i]] = vrh[0][i];
                }
            }
            if (v1) {
                __half* qsn = qsb + (nbase + 1) * TILE_H;
                __half* vsn = vsb + (nbase + 1) * TILE_H;
                #pragma unroll
                for (int i = 0; i < 4; ++i) {
                    *(uint2*)&qsn[qrow[i] * ASTH + qcol[i]] = qrh[1][i];
                    *(uint2*)&vsn[qrow[i] * ASTH + qcol[i]] = vrh[1][i];
                }
            }
            __syncthreads();
        }

        // peeled odd block (always the diagonal, sb = tb)
        if (nblocks & 1) {
            const int base = (npairs & 1) * 2;
            const uint32_t qb = qs32[base];
            const uint32_t vb = vs32[base];

            float s_c[4][4];
            #pragma unroll
            for (int nt = 0; nt < 4; ++nt)
                #pragma unroll
                for (int r = 0; r < 4; ++r) s_c[nt][r] = 0.f;
            #pragma unroll
            for (int kt = 0; kt < 4; ++kt) {
                #pragma unroll
                for (int p2 = 0; p2 < 2; ++p2) {
                    uint32_t B4[4];
                    ldsm4(B4, qb + qboff + (uint32_t)(p2 * 16 * ASTB + kt * 32));
                    mma16(s_c[2 * p2    ], A[kt], B4[0], B4[1]);
                    mma16(s_c[2 * p2 + 1], A[kt], B4[2], B4[3]);
                }
            }

            uint32_t pa[2][4];
            #pragma unroll
            for (int nt = 0; nt < 4; ++nt) {
                const int sc = wn * 32 + nt * 8 + 2 * t;
                float p0 = softplus_f(s_c[nt][0] * 0.03125f);
                float p1 = softplus_f(s_c[nt][1] * 0.03125f);
                float p2 = softplus_f(s_c[nt][2] * 0.03125f);
                float p3 = softplus_f(s_c[nt][3] * 0.03125f);
                if (sc     > trow    ) p0 = 0.f;
                if (sc + 1 > trow    ) p1 = 0.f;
                if (sc     > trow + 8) p2 = 0.f;
                if (sc + 1 > trow + 8) p3 = 0.f;
                const int j = nt >> 1;
                if ((nt & 1) == 0) { pa[j][0] = f2h2(p0, p1); pa[j][1] = f2h2(p2, p3); }
                else               { pa[j][2] = f2h2(p0, p1); pa[j][3] = f2h2(p2, p3); }
            }

            #pragma unroll
            for (int j = 0; j < 2; ++j) {
                const uint32_t vjb = vb + (uint32_t)((wn * 32 + j * 16) * ASTB) + vboff;
                #pragma unroll
                for (int q = 0; q < 4; ++q) {
                    uint32_t B4[4];
                    ldsm4t(B4, vjb + (uint32_t)(q * 32));
                    mma16(o[2 * q    ], pa[j], B4[0], B4[1]);
                    mma16(o[2 * q + 1], pa[j], B4[2], B4[3]);
                }
            }
            __syncthreads();
        }

        // cross-wn reduction (once per t-block): wn=1 stages, wn=0 adds+writes
        if (wn == 1) {
            #pragma unroll
            for (int nt = 0; nt < 8; ++nt) {
                const int col = nt * 8 + 2 * t;
                *(float2*)&stage[(wm * 16 + g    ) * 64 + col] = make_float2(o[nt][0], o[nt][1]);
                *(float2*)&stage[(wm * 16 + g + 8) * 64 + col] = make_float2(o[nt][2], o[nt][3]);
            }
        }
        __syncthreads();
        if (wn == 0) {
            const size_t row0 = (size_t)b * SEQ + tb * 64 + trow;
            #pragma unroll
            for (int nt = 0; nt < 8; ++nt) {
                const int col = nt * 8 + 2 * t;
                float2 s0 = *(const float2*)&stage[(wm * 16 + g    ) * 64 + col];
                float2 s1 = *(const float2*)&stage[(wm * 16 + g + 8) * 64 + col];
                *(float2*)&out[(row0    ) * HEAD + col] = make_float2(o[nt][0] + s0.x, o[nt][1] + s0.y);
                *(float2*)&out[(row0 + 8) * HEAD + col] = make_float2(o[nt][2] + s1.x, o[nt][3] + s1.y);
            }
        }
        __syncthreads();
    }
}

// ---------------------------------------------------------------------------
extern "C" void kernel_launch(void* const* d_in, const int* in_sizes, int n_in,
                              void* d_out, int out_size)
{
    const float* x  = (const float*)d_in[0];
    const float* Wk = (const float*)d_in[1];
    const float* bk = (const float*)d_in[2];
    const float* Wq = (const float*)d_in[3];
    const float* bq = (const float*)d_in[4];
    const float* Wv = (const float*)d_in[5];
    const float* bv = (const float*)d_in[6];
    float* out = (float*)d_out;

    static int init = 0;
    if (!init) {
        cudaFuncSetAttribute(attn_kernel, cudaFuncAttributeMaxDynamicSharedMemorySize, ATTN_SMEM);
        cudaFuncSetAttribute(proj_mma_kernel, cudaFuncAttributeMaxDynamicSharedMemorySize, PROJ_SMEM);
        init = 1;
    }

    dim3 wg(NEMB / 16, 3);
    wt_kernel<<<wg, 256>>>(Wk, Wq, Wv);

    proj_mma_kernel<<<MTOT / 128, 256, PROJ_SMEM>>>(x, bk, bq, bv);

    dim3 ag(NTB / 2, BATCH);
    attn_kernel<<<ag, 256, ATTN_SMEM>>>(out);
}